// round 15
// baseline (speedup 1.0000x reference)
#include <cuda_runtime.h>
#include <cstddef>

#define N_STEPS 4096
#define NU 8
#define R 256
#define NX 64
#define NY 8
#define L 16
#define C_CHUNKS (N_STEPS / L)   // 256
#define QTOT (NU * L)            // 128
#define NSUP 16                  // superchunks
#define SUBC 16                  // chunks per superchunk

typedef unsigned long long ull;

// Scratch (device globals)
__device__ float g_KcatT[QTOT * NX];
__device__ float g_AL[NX * NX];                       // A^16
__device__ float g_A256[NX * NX];                     // A^256
__device__ float g_A16pT[NSUP * NX * NX];             // [t][k][i] = (A^16t)[i][k]
__device__ float g_buf[(size_t)C_CHUNKS * NX * R];    // Pfin -> Xloc -> Xstart
__device__ float g_Pfin2[NSUP * NX * R];
__device__ float g_Xstart2[NSUP * NX * R];

// ---------------- packed f32x2 helpers ----------------
__device__ __forceinline__ ull pack2(float lo, float hi) {
    ull v; asm("mov.b64 %0,{%1,%2};" : "=l"(v) : "f"(lo), "f"(hi)); return v;
}
__device__ __forceinline__ void unpack2(ull v, float& lo, float& hi) {
    asm("mov.b64 {%0,%1},%2;" : "=f"(lo), "=f"(hi) : "l"(v));
}
__device__ __forceinline__ void fma2ip(ull& d, ull a, ull b) {
    asm("fma.rn.f32x2 %0,%1,%2,%0;" : "+l"(d) : "l"(a), "l"(b));
}

// ---------------------------------------------------------------------------
// Kernel 0: K-stack by doubling + A^16, then A^(16t) stack (transposed) and
// A^256 by serial chaining. 1 CTA, 512 threads, all matmuls in smem.
// ---------------------------------------------------------------------------
extern __shared__ float psm[];
__global__ void k_precompute(const float* __restrict__ A, const float* __restrict__ B) {
    float* sP = psm;
    float* sQ = psm + 4096;
    float* sW = psm + 8192;      // 8192 floats
    const int t = threadIdx.x;
    const int i = t >> 3;
    const int g = t & 7;

    for (int idx = t; idx < NX * NX; idx += 512) sP[idx] = A[idx];
    for (int idx = t; idx < NX * NU; idx += 512)
        sW[(idx / NU) * QTOT + (idx % NU)] = B[idx];
    __syncthreads();

    float* p = sP;
    float* q = sQ;
    int w = NU;
    for (int m = 0; m < 4; m++) {
        const int cw = w >> 3;
        if (cw == 1) {
            float s0 = 0.f, s1 = 0.f, s2 = 0.f, s3 = 0.f;
            #pragma unroll 4
            for (int k = 0; k < NX; k += 4) {
                s0 += p[i * NX + k + 0] * sW[(k + 0) * QTOT + g];
                s1 += p[i * NX + k + 1] * sW[(k + 1) * QTOT + g];
                s2 += p[i * NX + k + 2] * sW[(k + 2) * QTOT + g];
                s3 += p[i * NX + k + 3] * sW[(k + 3) * QTOT + g];
            }
            sW[i * QTOT + w + g] = (s0 + s1) + (s2 + s3);
        } else {
            const int jc0 = g * cw;
            const int nv = cw >> 1;
            ull acc[4] = {0ull, 0ull, 0ull, 0ull};
            for (int k = 0; k < NX; k++) {
                float a = p[i * NX + k];
                ull pk = pack2(a, a);
                const ull* wr = (const ull*)(sW + k * QTOT + jc0);
                #pragma unroll
                for (int v = 0; v < 4; v++)
                    if (v < nv) fma2ip(acc[v], pk, wr[v]);
            }
            ull* out = (ull*)(sW + i * QTOT + w + jc0);
            #pragma unroll
            for (int v = 0; v < 4; v++)
                if (v < nv) out[v] = acc[v];
        }
        {
            const int jb = g * 8;
            ull acc[4] = {0ull, 0ull, 0ull, 0ull};
            for (int k = 0; k < NX; k++) {
                float a = p[i * NX + k];
                ull pk = pack2(a, a);
                const ulonglong2* pr = (const ulonglong2*)(p + k * NX + jb);
                ulonglong2 w0 = pr[0], w1 = pr[1];
                fma2ip(acc[0], pk, w0.x);
                fma2ip(acc[1], pk, w0.y);
                fma2ip(acc[2], pk, w1.x);
                fma2ip(acc[3], pk, w1.y);
            }
            ull* out = (ull*)(q + i * NX + jb);
            out[0] = acc[0]; out[1] = acc[1]; out[2] = acc[2]; out[3] = acc[3];
        }
        __syncthreads();
        float* tmp = p; p = q; q = tmp;
        w <<= 1;
    }
    // p = A^16
    for (int idx = t; idx < NX * NX; idx += 512) g_AL[idx] = p[idx];
    for (int idx = t; idx < NX * QTOT; idx += 512) {
        int ii = idx >> 7, col = idx & 127;
        int s = col >> 3, j = col & 7;
        g_KcatT[(((L - 1 - s) * NU + j) * NX) + ii] = sW[ii * QTOT + col];
    }
    __syncthreads();

    // ---- A^(16t) stack (t=0..15, transposed) and A^256, chained vs p=A^16 ----
    float* M  = sW;          // 4096
    float* Mn = sW + 4096;   // 4096
    for (int idx = t; idx < 4096; idx += 512)
        M[idx] = ((idx >> 6) == (idx & 63)) ? 1.f : 0.f;
    __syncthreads();
    for (int tt = 0; tt < NSUP; tt++) {
        // store transposed: g_A16pT[tt][k*64+i] = M[i][k]
        for (int idx = t; idx < 4096; idx += 512) {
            int k = idx >> 6, ii = idx & 63;
            g_A16pT[tt * 4096 + idx] = M[ii * 64 + k];
        }
        // Mn = M @ A^16
        for (int idx = t; idx < 4096; idx += 512) {
            int ii = idx >> 6, j = idx & 63;
            float a0 = 0.f, a1 = 0.f, a2 = 0.f, a3 = 0.f;
            #pragma unroll 4
            for (int k = 0; k < 64; k += 4) {
                a0 += M[ii * 64 + k + 0] * p[(k + 0) * 64 + j];
                a1 += M[ii * 64 + k + 1] * p[(k + 1) * 64 + j];
                a2 += M[ii * 64 + k + 2] * p[(k + 2) * 64 + j];
                a3 += M[ii * 64 + k + 3] * p[(k + 3) * 64 + j];
            }
            Mn[idx] = (a0 + a1) + (a2 + a3);
        }
        __syncthreads();
        float* tmp = M; M = Mn; Mn = tmp;
    }
    // M = A^256
    for (int idx = t; idx < 4096; idx += 512) g_A256[idx] = M[idx];
}

// ---------------------------------------------------------------------------
// Kernel 1 (R9): Pfin -> g_buf.
// ---------------------------------------------------------------------------
__global__ void k_phase1(const float* __restrict__ u) {
    __shared__ __align__(16) float sU[64 * 64];
    __shared__ __align__(16) float sKT[64 * 64];
    const int c = blockIdx.x;
    const int r0 = blockIdx.y * 64;
    const int t = threadIdx.x;
    const int r = t & 63;
    const int ig = t >> 6;

    ull acc2[8];
    #pragma unroll
    for (int m = 0; m < 8; m++) acc2[m] = 0ull;
    const float* Uc = u + (size_t)c * L * NU * R;

    for (int qb = 0; qb < QTOT / 64; qb++) {
        __syncthreads();
        #pragma unroll
        for (int m = 0; m < 16; m++) {
            int qq = m * 4 + ig;
            sU[qq * 64 + r] = Uc[(size_t)(qb * 64 + qq) * R + r0 + r];
        }
        for (int idx = t; idx < 4096; idx += 256)
            sKT[idx] = g_KcatT[qb * 64 * 64 + idx];
        __syncthreads();
        #pragma unroll 8
        for (int qq = 0; qq < 64; qq++) {
            float uval = sU[qq * 64 + r];
            ull uv = pack2(uval, uval);
            const ulonglong2* k2p = (const ulonglong2*)(sKT + qq * 64 + ig * 16);
            #pragma unroll
            for (int m2 = 0; m2 < 4; m2++) {
                ulonglong2 kk = k2p[m2];
                fma2ip(acc2[2 * m2 + 0], kk.x, uv);
                fma2ip(acc2[2 * m2 + 1], kk.y, uv);
            }
        }
    }
    #pragma unroll
    for (int m = 0; m < 8; m++) {
        float lo, hi; unpack2(acc2[m], lo, hi);
        int i = ig * 16 + 2 * m;
        g_buf[((size_t)c * NX + i) * R + r0 + r]     = lo;
        g_buf[((size_t)c * NX + i + 1) * R + r0 + r] = hi;
    }
}

// shared step macro for scan kernels
#define SCAN_CORE(RB, WB, PF)                                                 \
    {                                                                         \
        const ull* xsrc = (const ull*)&sxf[RB][r][0];                         \
        ull A0 = 0ull, A1 = 0ull, A2 = 0ull, A3 = 0ull;                       \
        _Pragma("unroll")                                                     \
        for (int j2 = 0; j2 < 32; j2 += 4) {                                  \
            fma2ip(A0, a2[j2 + 0], xsrc[j2 + 0]);                             \
            fma2ip(A1, a2[j2 + 1], xsrc[j2 + 1]);                             \
            fma2ip(A2, a2[j2 + 2], xsrc[j2 + 2]);                             \
            fma2ip(A3, a2[j2 + 3], xsrc[j2 + 3]);                             \
        }                                                                     \
        float s0, s1, s2, s3, s4, s5, s6, s7;                                 \
        unpack2(A0, s0, s1); unpack2(A1, s2, s3);                             \
        unpack2(A2, s4, s5); unpack2(A3, s6, s7);                             \
        xi = (((s0 + s1) + (s2 + s3)) + ((s4 + s5) + (s6 + s7))) + (PF);      \
        sxf[WB][r][i] = xi;                                                   \
        __syncthreads();                                                      \
    }

// ---------------------------------------------------------------------------
// Kernel 2a: parallel local scans (zero-init), 16 iters, in-place Xloc,
// emits Pfin2. Grid (128, 16 superchunks), block 128.
// ---------------------------------------------------------------------------
__global__ void k_phase2a() {
    __shared__ __align__(16) float sxf[2][2][NX];
    const int t = threadIdx.x;
    const int r = t & 1;
    const int i = t >> 1;
    const int rg = blockIdx.x * 2 + r;
    const int s = blockIdx.y;

    ull a2[32];
    const ull* arow = (const ull*)(g_AL + i * NX);   // A^16
    #pragma unroll
    for (int j2 = 0; j2 < 32; j2++) a2[j2] = arow[j2];

    float xi = 0.f;
    sxf[0][r][i] = 0.f;
    __syncthreads();

    const size_t stride = (size_t)NX * R;
    float* gb = g_buf + (size_t)s * SUBC * stride + (size_t)i * R + rg;

    float pf0 = gb[0 * stride];
    float pf1 = gb[1 * stride];
    float pf2 = gb[2 * stride];
    float pf3 = gb[3 * stride];

#define P2A_STEP(CC, PF, RB, WB)                                              \
    {                                                                         \
        gb[(size_t)(CC) * stride] = xi;                                       \
        float pfnew = ((CC) + 4 < SUBC) ? gb[(size_t)((CC) + 4) * stride]     \
                                        : 0.f;                                \
        SCAN_CORE(RB, WB, PF);                                                \
        (PF) = pfnew;                                                         \
    }
    #pragma unroll
    for (int c = 0; c < SUBC; c += 4) {
        P2A_STEP(c + 0, pf0, 0, 1);
        P2A_STEP(c + 1, pf1, 1, 0);
        P2A_STEP(c + 2, pf2, 0, 1);
        P2A_STEP(c + 3, pf3, 1, 0);
    }
#undef P2A_STEP
    g_Pfin2[((size_t)s * NX + i) * R + rg] = xi;
}

// ---------------------------------------------------------------------------
// Kernel 2b: superchunk scan (16 iters, A^256). 128 CTAs x 128 thr.
// ---------------------------------------------------------------------------
__global__ void k_phase2b(const float* __restrict__ x0) {
    __shared__ __align__(16) float sxf[2][2][NX];
    const int t = threadIdx.x;
    const int r = t & 1;
    const int i = t >> 1;
    const int rg = blockIdx.x * 2 + r;

    ull a2[32];
    const ull* arow = (const ull*)(g_A256 + i * NX);
    #pragma unroll
    for (int j2 = 0; j2 < 32; j2++) a2[j2] = arow[j2];

    float xi = x0[i * R + rg];
    sxf[0][r][i] = xi;
    __syncthreads();

    #pragma unroll
    for (int s = 0; s < NSUP; s += 2) {
        {
            float pf = g_Pfin2[((size_t)s * NX + i) * R + rg];
            g_Xstart2[((size_t)s * NX + i) * R + rg] = xi;
            SCAN_CORE(0, 1, pf);
        }
        {
            float pf = g_Pfin2[((size_t)(s + 1) * NX + i) * R + rg];
            g_Xstart2[((size_t)(s + 1) * NX + i) * R + rg] = xi;
            SCAN_CORE(1, 0, pf);
        }
    }
}

// ---------------------------------------------------------------------------
// Kernel 2c: fill Xstart[16s+t] = A^(16t) @ Xstart2[s] + Xloc (in-place g_buf).
// Grid (256 chunks, 4 r-blocks), 256 threads (phase1-shaped).
// ---------------------------------------------------------------------------
__global__ void k_phase2c() {
    __shared__ __align__(16) float sU[64 * 64];
    __shared__ __align__(16) float sKT[64 * 64];
    const int c = blockIdx.x;
    const int s = c >> 4, tt = c & 15;
    const int r0 = blockIdx.y * 64;
    const int t = threadIdx.x;
    const int r = t & 63;
    const int ig = t >> 6;

    #pragma unroll
    for (int m = 0; m < 16; m++) {
        int qq = m * 4 + ig;
        sU[qq * 64 + r] = g_Xstart2[((size_t)s * NX + qq) * R + r0 + r];
    }
    for (int idx = t; idx < 4096; idx += 256)
        sKT[idx] = g_A16pT[tt * 4096 + idx];
    __syncthreads();

    ull acc2[8];
    #pragma unroll
    for (int m = 0; m < 8; m++) acc2[m] = 0ull;

    #pragma unroll 8
    for (int qq = 0; qq < 64; qq++) {
        float uval = sU[qq * 64 + r];
        ull uv = pack2(uval, uval);
        const ulonglong2* k2p = (const ulonglong2*)(sKT + qq * 64 + ig * 16);
        #pragma unroll
        for (int m2 = 0; m2 < 4; m2++) {
            ulonglong2 kk = k2p[m2];
            fma2ip(acc2[2 * m2 + 0], kk.x, uv);
            fma2ip(acc2[2 * m2 + 1], kk.y, uv);
        }
    }
    #pragma unroll
    for (int m = 0; m < 8; m++) {
        float lo, hi; unpack2(acc2[m], lo, hi);
        int i = ig * 16 + 2 * m;
        size_t o = ((size_t)c * NX + i) * R + r0 + r;
        g_buf[o]     = lo + g_buf[o];        // + Xloc
        g_buf[o + R] = hi + g_buf[o + R];
    }
}

// ---------------------------------------------------------------------------
// Kernel 3 (R7/R14 best): TWO columns per thread, packed f32x2 in-place.
// ---------------------------------------------------------------------------
extern __shared__ __align__(16) char dsmem[];

__global__ void __launch_bounds__(64) k_phase3(
    const float* __restrict__ u, const float* __restrict__ A,
    const float* __restrict__ B, const float* __restrict__ Cy,
    const float* __restrict__ D,
    float* __restrict__ outY, float* __restrict__ outX)
{
    ull*   xs  = (ull*)dsmem;
    ull*   sA2 = (ull*)(dsmem + 32768);
    ull*   sB2 = (ull*)(dsmem + 32768 + 16384);
    ull*   sC2 = (ull*)(dsmem + 32768 + 16384 + 2048);
    float* sD  = (float*)(dsmem + 32768 + 16384 + 4096);

    const int tid = threadIdx.x;
    const int c = blockIdx.x;
    const int rA = blockIdx.y * 128 + tid;

    for (int idx = tid; idx < 64 * 32; idx += 64) {
        int j = idx >> 5, i2 = idx & 31;
        sA2[idx] = pack2(A[(2 * i2) * NX + j], A[(2 * i2 + 1) * NX + j]);
    }
    for (int idx = tid; idx < NU * 32; idx += 64) {
        int j = idx >> 5, i2 = idx & 31;
        sB2[idx] = pack2(B[(2 * i2) * NU + j], B[(2 * i2 + 1) * NU + j]);
    }
    for (int idx = tid; idx < NY * 32; idx += 64) {
        int o = idx >> 5, j2 = idx & 31;
        sC2[idx] = pack2(Cy[o * NX + 2 * j2], Cy[o * NX + 2 * j2 + 1]);
    }
    if (tid < NY * NU) sD[tid] = D[tid];

    ull acc2a[32], acc2b[32];
    {
        const float* xsa = g_buf + (size_t)c * NX * R + rA;
        #pragma unroll
        for (int k = 0; k < 32; k++) {
            acc2a[k] = pack2(xsa[(2 * k) * R], xsa[(2 * k + 1) * R]);
            acc2b[k] = pack2(xsa[(2 * k) * R + 64], xsa[(2 * k + 1) * R + 64]);
        }
    }
    __syncthreads();

    const float* upa = u    + (size_t)c * L * NU * R + rA;
    float*       ypa = outY + (size_t)c * L * NY * R + rA;
    float*       xpa = outX + (size_t)c * L * NX * R + rA;

    #pragma unroll 1
    for (int step = 0; step < L; step++) {
        float ua[NU], ub[NU];
        #pragma unroll
        for (int j = 0; j < NU; j++) {
            ua[j] = upa[j * R];
            ub[j] = upa[j * R + 64];
        }

        #pragma unroll 2
        for (int o = 0; o < NY; o++) {
            ull ya = 0ull, yb = 0ull;
            const ulonglong2* c2 = (const ulonglong2*)(sC2 + o * 32);
            #pragma unroll
            for (int k2 = 0; k2 < 16; k2++) {
                ulonglong2 cc = c2[k2];
                fma2ip(ya, cc.x, acc2a[2 * k2 + 0]);
                fma2ip(ya, cc.y, acc2a[2 * k2 + 1]);
                fma2ip(yb, cc.x, acc2b[2 * k2 + 0]);
                fma2ip(yb, cc.y, acc2b[2 * k2 + 1]);
            }
            float la, ha; unpack2(ya, la, ha);
            float lb, hb; unpack2(yb, lb, hb);
            float dsa = 0.f, dsb = 0.f;
            #pragma unroll
            for (int j = 0; j < NU; j++) {
                float dv = sD[o * NU + j];
                dsa += dv * ua[j];
                dsb += dv * ub[j];
            }
            ypa[o * R]      = (la + ha) + dsa;
            ypa[o * R + 64] = (lb + hb) + dsb;
        }

        #pragma unroll
        for (int k = 0; k < 32; k++) {
            float la, ha; unpack2(acc2a[k], la, ha);
            float lb, hb; unpack2(acc2b[k], lb, hb);
            xpa[(2 * k) * R]          = la;
            xpa[(2 * k + 1) * R]      = ha;
            xpa[(2 * k) * R + 64]     = lb;
            xpa[(2 * k + 1) * R + 64] = hb;
            xs[k * 128 + tid]      = acc2a[k];
            xs[k * 128 + 64 + tid] = acc2b[k];
        }

        {
            #pragma unroll
            for (int k = 0; k < 32; k++) { acc2a[k] = 0ull; acc2b[k] = 0ull; }
            #pragma unroll 2
            for (int j = 0; j < NU; j++) {
                ull uaj = pack2(ua[j], ua[j]);
                ull ubj = pack2(ub[j], ub[j]);
                const ulonglong2* bj = (const ulonglong2*)(sB2 + j * 32);
                #pragma unroll
                for (int k2 = 0; k2 < 16; k2++) {
                    ulonglong2 bb = bj[k2];
                    fma2ip(acc2a[2 * k2 + 0], bb.x, uaj);
                    fma2ip(acc2a[2 * k2 + 1], bb.y, uaj);
                    fma2ip(acc2b[2 * k2 + 0], bb.x, ubj);
                    fma2ip(acc2b[2 * k2 + 1], bb.y, ubj);
                }
            }
        }

        #pragma unroll 2
        for (int j2 = 0; j2 < 32; j2++) {
            ull pa = xs[j2 * 128 + tid];
            ull pb = xs[j2 * 128 + 64 + tid];
            float xa0, xa1; unpack2(pa, xa0, xa1);
            float xb0, xb1; unpack2(pb, xb0, xb1);
            ull sa0 = pack2(xa0, xa0), sa1 = pack2(xa1, xa1);
            ull sb0 = pack2(xb0, xb0), sb1 = pack2(xb1, xb1);
            const ulonglong2* A0 = (const ulonglong2*)(sA2 + (2 * j2) * 32);
            const ulonglong2* A1 = (const ulonglong2*)(sA2 + (2 * j2 + 1) * 32);
            #pragma unroll
            for (int k2 = 0; k2 < 16; k2++) {
                ulonglong2 aa = A0[k2];
                fma2ip(acc2a[2 * k2 + 0], aa.x, sa0);
                fma2ip(acc2a[2 * k2 + 1], aa.y, sa0);
                fma2ip(acc2b[2 * k2 + 0], aa.x, sb0);
                fma2ip(acc2b[2 * k2 + 1], aa.y, sb0);
                ulonglong2 ab = A1[k2];
                fma2ip(acc2a[2 * k2 + 0], ab.x, sa1);
                fma2ip(acc2a[2 * k2 + 1], ab.y, sa1);
                fma2ip(acc2b[2 * k2 + 0], ab.x, sb1);
                fma2ip(acc2b[2 * k2 + 1], ab.y, sb1);
            }
        }

        upa += NU * R;
        ypa += NY * R;
        xpa += NX * R;
    }
}

#define SMEM_P3 (32768 + 16384 + 2048 + 2048 + 256)
#define SMEM_P0 ((4096 + 4096 + 8192) * 4)

// ---------------------------------------------------------------------------
extern "C" void kernel_launch(void* const* d_in, const int* in_sizes, int n_in,
                              void* d_out, int out_size) {
    const float* u  = (const float*)d_in[0];
    const float* x0 = (const float*)d_in[1];
    const float* A  = (const float*)d_in[2];
    const float* B  = (const float*)d_in[3];
    const float* Cy = (const float*)d_in[4];
    const float* D  = (const float*)d_in[5];
    float* outY = (float*)d_out;
    float* outX = (float*)d_out + (size_t)N_STEPS * NY * R;

    cudaFuncSetAttribute(k_phase3, cudaFuncAttributeMaxDynamicSharedMemorySize, SMEM_P3);
    cudaFuncSetAttribute(k_precompute, cudaFuncAttributeMaxDynamicSharedMemorySize, SMEM_P0);

    k_precompute<<<1, 512, SMEM_P0>>>(A, B);
    k_phase1<<<dim3(C_CHUNKS, R / 64), 256>>>(u);
    k_phase2a<<<dim3(R / 2, NSUP), 128>>>();
    k_phase2b<<<R / 2, 128>>>(x0);
    k_phase2c<<<dim3(C_CHUNKS, R / 64), 256>>>();
    k_phase3<<<dim3(C_CHUNKS, 2), 64, SMEM_P3>>>(u, A, B, Cy, D, outY, outX);
}

// round 16
// speedup vs baseline: 1.0264x; 1.0264x over previous
#include <cuda_runtime.h>
#include <cstddef>

#define N_STEPS 4096
#define NU 8
#define R 256
#define NX 64
#define NY 8
#define L 16
#define C_CHUNKS (N_STEPS / L)   // 256
#define QTOT (NU * L)            // 128
#define NSUP 16
#define SUBC 16

typedef unsigned long long ull;

// Scratch (device globals)
__device__ ull   g_K2[QTOT * 32];                    // [q][i2] pack2(K[2i2][q],K[2i2+1][q])
__device__ ull   g_A16p2[NSUP * NX * 32];            // [tt][j][i2] packed cols of A^(16tt)
__device__ float g_A256[NX * NX];
__device__ float g_buf[(size_t)C_CHUNKS * NX * R];   // Xloc
__device__ float g_Pfin2[NSUP * NX * R];
__device__ float g_Xstart2[NSUP * NX * R];

// ---------------- packed f32x2 helpers ----------------
__device__ __forceinline__ ull pack2(float lo, float hi) {
    ull v; asm("mov.b64 %0,{%1,%2};" : "=l"(v) : "f"(lo), "f"(hi)); return v;
}
__device__ __forceinline__ void unpack2(ull v, float& lo, float& hi) {
    asm("mov.b64 {%0,%1},%2;" : "=f"(lo), "=f"(hi) : "l"(v));
}
__device__ __forceinline__ void fma2ip(ull& d, ull a, ull b) {
    asm("fma.rn.f32x2 %0,%1,%2,%0;" : "+l"(d) : "l"(a), "l"(b));
}

// ---------------------------------------------------------------------------
// Kernel 0: K-stack (doubling), packed K2; A^(16t) packed stack; A^256.
// 1 CTA, 512 threads, all in smem.
// ---------------------------------------------------------------------------
extern __shared__ float psm[];
__global__ void k_precompute(const float* __restrict__ A, const float* __restrict__ B) {
    float* sP = psm;             // 4096
    float* sQ = psm + 4096;      // 4096
    float* sW = psm + 8192;      // 8192: [i][col], col = s*8+j, (A^s B)[i][j]
    const int t = threadIdx.x;   // 512
    const int i = t >> 3;
    const int g = t & 7;

    for (int idx = t; idx < NX * NX; idx += 512) sP[idx] = A[idx];
    for (int idx = t; idx < NX * NU; idx += 512)
        sW[(idx / NU) * QTOT + (idx % NU)] = B[idx];
    __syncthreads();

    float* p = sP;
    float* q = sQ;
    int w = NU;
    for (int m = 0; m < 4; m++) {
        const int cw = w >> 3;
        if (cw == 1) {
            float s0 = 0.f, s1 = 0.f, s2 = 0.f, s3 = 0.f;
            #pragma unroll 4
            for (int k = 0; k < NX; k += 4) {
                s0 += p[i * NX + k + 0] * sW[(k + 0) * QTOT + g];
                s1 += p[i * NX + k + 1] * sW[(k + 1) * QTOT + g];
                s2 += p[i * NX + k + 2] * sW[(k + 2) * QTOT + g];
                s3 += p[i * NX + k + 3] * sW[(k + 3) * QTOT + g];
            }
            sW[i * QTOT + w + g] = (s0 + s1) + (s2 + s3);
        } else {
            const int jc0 = g * cw;
            const int nv = cw >> 1;
            ull acc[4] = {0ull, 0ull, 0ull, 0ull};
            for (int k = 0; k < NX; k++) {
                float a = p[i * NX + k];
                ull pk = pack2(a, a);
                const ull* wr = (const ull*)(sW + k * QTOT + jc0);
                #pragma unroll
                for (int v = 0; v < 4; v++)
                    if (v < nv) fma2ip(acc[v], pk, wr[v]);
            }
            ull* out = (ull*)(sW + i * QTOT + w + jc0);
            #pragma unroll
            for (int v = 0; v < 4; v++)
                if (v < nv) out[v] = acc[v];
        }
        {
            const int jb = g * 8;
            ull acc[4] = {0ull, 0ull, 0ull, 0ull};
            for (int k = 0; k < NX; k++) {
                float a = p[i * NX + k];
                ull pk = pack2(a, a);
                const ulonglong2* pr = (const ulonglong2*)(p + k * NX + jb);
                ulonglong2 w0 = pr[0], w1 = pr[1];
                fma2ip(acc[0], pk, w0.x);
                fma2ip(acc[1], pk, w0.y);
                fma2ip(acc[2], pk, w1.x);
                fma2ip(acc[3], pk, w1.y);
            }
            ull* out = (ull*)(q + i * NX + jb);
            out[0] = acc[0]; out[1] = acc[1]; out[2] = acc[2]; out[3] = acc[3];
        }
        __syncthreads();
        float* tmp = p; p = q; q = tmp;
        w <<= 1;
    }
    // p = A^16. Emit packed K2: q = (15-s)*8+j, pairs over i.
    for (int idx = t; idx < QTOT * 32; idx += 512) {
        int qq = idx >> 5, i2 = idx & 31;
        int tt = qq >> 3, j = qq & 7;
        int col = (15 - tt) * 8 + j;
        g_K2[idx] = pack2(sW[(2 * i2) * QTOT + col], sW[(2 * i2 + 1) * QTOT + col]);
    }
    __syncthreads();

    // A^(16t) packed stack + A^256 (chained against p = A^16)
    float* M  = sW;
    float* Mn = sW + 4096;
    for (int idx = t; idx < 4096; idx += 512)
        M[idx] = ((idx >> 6) == (idx & 63)) ? 1.f : 0.f;
    __syncthreads();
    for (int tt = 0; tt < NSUP; tt++) {
        // packed store: g_A16p2[tt][j*32+i2] = pack2(M[2i2][j], M[2i2+1][j])
        for (int idx = t; idx < 2048; idx += 512) {
            int j = idx >> 5, i2 = idx & 31;
            g_A16p2[tt * 2048 + idx] = pack2(M[(2 * i2) * 64 + j], M[(2 * i2 + 1) * 64 + j]);
        }
        for (int idx = t; idx < 4096; idx += 512) {
            int ii = idx >> 6, j = idx & 63;
            float a0 = 0.f, a1 = 0.f, a2 = 0.f, a3 = 0.f;
            #pragma unroll 4
            for (int k = 0; k < 64; k += 4) {
                a0 += M[ii * 64 + k + 0] * p[(k + 0) * 64 + j];
                a1 += M[ii * 64 + k + 1] * p[(k + 1) * 64 + j];
                a2 += M[ii * 64 + k + 2] * p[(k + 2) * 64 + j];
                a3 += M[ii * 64 + k + 3] * p[(k + 3) * 64 + j];
            }
            Mn[idx] = (a0 + a1) + (a2 + a3);
        }
        __syncthreads();
        float* tmp = M; M = Mn; Mn = tmp;
    }
    for (int idx = t; idx < 4096; idx += 512) g_A256[idx] = M[idx];
}

// ---------------------------------------------------------------------------
// Kernel P12A: fused Pfin-compute + local scan. Grid (NSUP, 16 r-blocks),
// 256 threads = (col 0..15) x (rowgroup 0..15, 4 rows each). Writes Xloc
// (in g_buf) and Pfin2. Dynamic smem ~60.5KB.
// ---------------------------------------------------------------------------
extern __shared__ __align__(16) char fsm[];
__global__ void __launch_bounds__(256) k_p12a(const float* __restrict__ u) {
    ull*   sK2  = (ull*)fsm;                      // 32KB  [q][i2]
    ull*   sA16 = (ull*)(fsm + 32768);            // 16KB  [j][i2]
    float* sU   = (float*)(fsm + 49152);          // 8KB   [q][16]
    float* sx   = (float*)(fsm + 57344);          // 4KB   [j][16]
    const int t = threadIdx.x;                    // 256
    const int col = t & 15;
    const int rg  = t >> 4;                       // 0..15, rows 4rg..4rg+3 (i2 = 2rg, 2rg+1)
    const int s = blockIdx.x;
    const int rglob = blockIdx.y * 16 + col;

    for (int idx = t; idx < QTOT * 32; idx += 256) sK2[idx] = g_K2[idx];
    for (int idx = t; idx < NX * 32; idx += 256) sA16[idx] = g_A16p2[1 * 2048 + idx];
    for (int idx = t; idx < NX * 16 / 4; idx += 256) ((float4*)sx)[idx] = make_float4(0, 0, 0, 0);

    const float* ub = u + (size_t)s * SUBC * QTOT * R;
    float x0r = 0.f, x1r = 0.f, x2r = 0.f, x3r = 0.f;  // xold rows 4rg..4rg+3

    #pragma unroll 1
    for (int cc = 0; cc < SUBC; cc++) {
        __syncthreads();   // sx(xold) visible; sU free
        // stage U chunk: [128 q][16 cols]
        for (int idx = t; idx < QTOT * 16; idx += 256) {
            int qq = idx >> 4, rr = idx & 15;
            sU[idx] = ub[((size_t)cc * QTOT + qq) * R + blockIdx.y * 16 + rr];
        }
        __syncthreads();

        // pfin = K @ Uc (my 2 packed row-pairs, my col)
        ull p0 = 0ull, p1 = 0ull;
        #pragma unroll 4
        for (int qq = 0; qq < QTOT; qq++) {
            float uv = sU[qq * 16 + col];
            ull us = pack2(uv, uv);
            const ulonglong2* kk = (const ulonglong2*)(sK2 + qq * 32 + 2 * rg);
            ulonglong2 kv = *kk;
            fma2ip(p0, kv.x, us);
            fma2ip(p1, kv.y, us);
        }
        // ax = A^16 @ xold (reads full sx column)
        ull a0 = 0ull, a1 = 0ull;
        #pragma unroll 4
        for (int j = 0; j < NX; j++) {
            float xv = sx[j * 16 + col];
            ull xsp = pack2(xv, xv);
            const ulonglong2* aa = (const ulonglong2*)(sA16 + j * 32 + 2 * rg);
            ulonglong2 av = *aa;
            fma2ip(a0, av.x, xsp);
            fma2ip(a1, av.y, xsp);
        }
        // store Xloc[c] = xold; advance
        {
            float* gx = g_buf + (((size_t)(s * SUBC + cc) * NX + 4 * rg) * R) + rglob;
            gx[0 * R] = x0r; gx[1 * R] = x1r; gx[2 * R] = x2r; gx[3 * R] = x3r;
        }
        float n0, n1, n2, n3, q0, q1, q2, q3;
        unpack2(a0, n0, n1); unpack2(a1, n2, n3);
        unpack2(p0, q0, q1); unpack2(p1, q2, q3);
        x0r = n0 + q0; x1r = n1 + q1; x2r = n2 + q2; x3r = n3 + q3;
        __syncthreads();   // all sx reads done
        sx[(4 * rg + 0) * 16 + col] = x0r;
        sx[(4 * rg + 1) * 16 + col] = x1r;
        sx[(4 * rg + 2) * 16 + col] = x2r;
        sx[(4 * rg + 3) * 16 + col] = x3r;
    }
    // Pfin2[s] = final local state
    float* gp = g_Pfin2 + ((size_t)s * NX + 4 * rg) * R + rglob;
    gp[0 * R] = x0r; gp[1 * R] = x1r; gp[2 * R] = x2r; gp[3 * R] = x3r;
}

// ---------------------------------------------------------------------------
// Kernel 2b (R15, measured 15us): superchunk scan (16 iters, A^256).
// ---------------------------------------------------------------------------
__global__ void k_phase2b(const float* __restrict__ x0) {
    __shared__ __align__(16) float sxf[2][2][NX];
    __shared__ __align__(16) float sA[NX * NX];
    const int t = threadIdx.x;  // 128
    const int r = t & 1;
    const int i = t >> 1;
    const int rg = blockIdx.x * 2 + r;

    for (int idx = t; idx < NX * NX; idx += 128) sA[idx] = g_A256[idx];

    ull a2[32];
    float xi = x0[i * R + rg];
    sxf[0][r][i] = xi;
    __syncthreads();
    const ull* arow = (const ull*)(sA + i * NX);
    #pragma unroll
    for (int j2 = 0; j2 < 32; j2++) a2[j2] = arow[j2];

#define SCAN_CORE(RB, WB, PF)                                                 \
    {                                                                         \
        const ull* xsrc = (const ull*)&sxf[RB][r][0];                         \
        ull A0 = 0ull, A1 = 0ull, A2 = 0ull, A3 = 0ull;                       \
        _Pragma("unroll")                                                     \
        for (int j2 = 0; j2 < 32; j2 += 4) {                                  \
            fma2ip(A0, a2[j2 + 0], xsrc[j2 + 0]);                             \
            fma2ip(A1, a2[j2 + 1], xsrc[j2 + 1]);                             \
            fma2ip(A2, a2[j2 + 2], xsrc[j2 + 2]);                             \
            fma2ip(A3, a2[j2 + 3], xsrc[j2 + 3]);                             \
        }                                                                     \
        float s0, s1, s2, s3, s4, s5, s6, s7;                                 \
        unpack2(A0, s0, s1); unpack2(A1, s2, s3);                             \
        unpack2(A2, s4, s5); unpack2(A3, s6, s7);                             \
        xi = (((s0 + s1) + (s2 + s3)) + ((s4 + s5) + (s6 + s7))) + (PF);      \
        sxf[WB][r][i] = xi;                                                   \
        __syncthreads();                                                      \
    }

    #pragma unroll
    for (int s = 0; s < NSUP; s += 2) {
        {
            float pf = g_Pfin2[((size_t)s * NX + i) * R + rg];
            g_Xstart2[((size_t)s * NX + i) * R + rg] = xi;
            SCAN_CORE(0, 1, pf);
        }
        {
            float pf = g_Pfin2[((size_t)(s + 1) * NX + i) * R + rg];
            g_Xstart2[((size_t)(s + 1) * NX + i) * R + rg] = xi;
            SCAN_CORE(1, 0, pf);
        }
    }
#undef SCAN_CORE
}

// ---------------------------------------------------------------------------
// Kernel 3 (R14 + fused start-state reconstruction):
// acc = A^(16tt) @ Xstart2[s] + Xloc[c], then the proven 2-col/thread loop.
// ---------------------------------------------------------------------------
extern __shared__ __align__(16) char dsmem[];

__global__ void __launch_bounds__(64) k_phase3(
    const float* __restrict__ u, const float* __restrict__ A,
    const float* __restrict__ B, const float* __restrict__ Cy,
    const float* __restrict__ D,
    float* __restrict__ outY, float* __restrict__ outX)
{
    ull*   xs  = (ull*)dsmem;                          // [32][128]
    ull*   sA2 = (ull*)(dsmem + 32768);                // [j][i2]
    ull*   sB2 = (ull*)(dsmem + 32768 + 16384);
    ull*   sC2 = (ull*)(dsmem + 32768 + 16384 + 2048);
    float* sD  = (float*)(dsmem + 32768 + 16384 + 4096);

    const int tid = threadIdx.x;                       // 64
    const int c = blockIdx.x;
    const int sup = c >> 4, tt = c & 15;
    const int rA = blockIdx.y * 128 + tid;

    // --- reconstruction: sA2 <- A^(16tt) packed; xs <- Xstart2[s] cols ---
    {
        const ulonglong2* src = (const ulonglong2*)(g_A16p2 + tt * 2048);
        ulonglong2* dst = (ulonglong2*)sA2;
        for (int idx = tid; idx < 1024; idx += 64) dst[idx] = src[idx];
        const float* x2 = g_Xstart2 + (size_t)sup * NX * R + rA;
        #pragma unroll
        for (int k = 0; k < 32; k++) {
            xs[k * 128 + tid]      = pack2(x2[(2 * k) * R], x2[(2 * k + 1) * R]);
            xs[k * 128 + 64 + tid] = pack2(x2[(2 * k) * R + 64], x2[(2 * k + 1) * R + 64]);
        }
    }
    // acc init = Xloc
    ull acc2a[32], acc2b[32];
    {
        const float* xl = g_buf + (size_t)c * NX * R + rA;
        #pragma unroll
        for (int k = 0; k < 32; k++) {
            acc2a[k] = pack2(xl[(2 * k) * R], xl[(2 * k + 1) * R]);
            acc2b[k] = pack2(xl[(2 * k) * R + 64], xl[(2 * k + 1) * R + 64]);
        }
    }
    __syncthreads();
    // acc += A^(16tt) @ Xstart2
    #pragma unroll 2
    for (int j2 = 0; j2 < 32; j2++) {
        ull pa = xs[j2 * 128 + tid];
        ull pb = xs[j2 * 128 + 64 + tid];
        float xa0, xa1; unpack2(pa, xa0, xa1);
        float xb0, xb1; unpack2(pb, xb0, xb1);
        ull sa0 = pack2(xa0, xa0), sa1 = pack2(xa1, xa1);
        ull sb0 = pack2(xb0, xb0), sb1 = pack2(xb1, xb1);
        const ulonglong2* A0 = (const ulonglong2*)(sA2 + (2 * j2) * 32);
        const ulonglong2* A1 = (const ulonglong2*)(sA2 + (2 * j2 + 1) * 32);
        #pragma unroll
        for (int k2 = 0; k2 < 16; k2++) {
            ulonglong2 aa = A0[k2];
            fma2ip(acc2a[2 * k2 + 0], aa.x, sa0);
            fma2ip(acc2a[2 * k2 + 1], aa.y, sa0);
            fma2ip(acc2b[2 * k2 + 0], aa.x, sb0);
            fma2ip(acc2b[2 * k2 + 1], aa.y, sb0);
            ulonglong2 ab = A1[k2];
            fma2ip(acc2a[2 * k2 + 0], ab.x, sa1);
            fma2ip(acc2a[2 * k2 + 1], ab.y, sa1);
            fma2ip(acc2b[2 * k2 + 0], ab.x, sb1);
            fma2ip(acc2b[2 * k2 + 1], ab.y, sb1);
        }
    }
    __syncthreads();

    // --- load real matrices ---
    for (int idx = tid; idx < 64 * 32; idx += 64) {
        int j = idx >> 5, i2 = idx & 31;
        sA2[idx] = pack2(A[(2 * i2) * NX + j], A[(2 * i2 + 1) * NX + j]);
    }
    for (int idx = tid; idx < NU * 32; idx += 64) {
        int j = idx >> 5, i2 = idx & 31;
        sB2[idx] = pack2(B[(2 * i2) * NU + j], B[(2 * i2 + 1) * NU + j]);
    }
    for (int idx = tid; idx < NY * 32; idx += 64) {
        int o = idx >> 5, j2 = idx & 31;
        sC2[idx] = pack2(Cy[o * NX + 2 * j2], Cy[o * NX + 2 * j2 + 1]);
    }
    if (tid < NY * NU) sD[tid] = D[tid];
    __syncthreads();

    const float* upa = u    + (size_t)c * L * NU * R + rA;
    float*       ypa = outY + (size_t)c * L * NY * R + rA;
    float*       xpa = outX + (size_t)c * L * NX * R + rA;

    #pragma unroll 1
    for (int step = 0; step < L; step++) {
        float ua[NU], ub[NU];
        #pragma unroll
        for (int j = 0; j < NU; j++) {
            ua[j] = upa[j * R];
            ub[j] = upa[j * R + 64];
        }

        #pragma unroll 2
        for (int o = 0; o < NY; o++) {
            ull ya = 0ull, yb = 0ull;
            const ulonglong2* c2 = (const ulonglong2*)(sC2 + o * 32);
            #pragma unroll
            for (int k2 = 0; k2 < 16; k2++) {
                ulonglong2 cc = c2[k2];
                fma2ip(ya, cc.x, acc2a[2 * k2 + 0]);
                fma2ip(ya, cc.y, acc2a[2 * k2 + 1]);
                fma2ip(yb, cc.x, acc2b[2 * k2 + 0]);
                fma2ip(yb, cc.y, acc2b[2 * k2 + 1]);
            }
            float la, ha; unpack2(ya, la, ha);
            float lb, hb; unpack2(yb, lb, hb);
            float dsa = 0.f, dsb = 0.f;
            #pragma unroll
            for (int j = 0; j < NU; j++) {
                float dv = sD[o * NU + j];
                dsa += dv * ua[j];
                dsb += dv * ub[j];
            }
            ypa[o * R]      = (la + ha) + dsa;
            ypa[o * R + 64] = (lb + hb) + dsb;
        }

        #pragma unroll
        for (int k = 0; k < 32; k++) {
            float la, ha; unpack2(acc2a[k], la, ha);
            float lb, hb; unpack2(acc2b[k], lb, hb);
            xpa[(2 * k) * R]          = la;
            xpa[(2 * k + 1) * R]      = ha;
            xpa[(2 * k) * R + 64]     = lb;
            xpa[(2 * k + 1) * R + 64] = hb;
            xs[k * 128 + tid]      = acc2a[k];
            xs[k * 128 + 64 + tid] = acc2b[k];
        }

        {
            #pragma unroll
            for (int k = 0; k < 32; k++) { acc2a[k] = 0ull; acc2b[k] = 0ull; }
            #pragma unroll 2
            for (int j = 0; j < NU; j++) {
                ull uaj = pack2(ua[j], ua[j]);
                ull ubj = pack2(ub[j], ub[j]);
                const ulonglong2* bj = (const ulonglong2*)(sB2 + j * 32);
                #pragma unroll
                for (int k2 = 0; k2 < 16; k2++) {
                    ulonglong2 bb = bj[k2];
                    fma2ip(acc2a[2 * k2 + 0], bb.x, uaj);
                    fma2ip(acc2a[2 * k2 + 1], bb.y, uaj);
                    fma2ip(acc2b[2 * k2 + 0], bb.x, ubj);
                    fma2ip(acc2b[2 * k2 + 1], bb.y, ubj);
                }
            }
        }

        #pragma unroll 2
        for (int j2 = 0; j2 < 32; j2++) {
            ull pa = xs[j2 * 128 + tid];
            ull pb = xs[j2 * 128 + 64 + tid];
            float xa0, xa1; unpack2(pa, xa0, xa1);
            float xb0, xb1; unpack2(pb, xb0, xb1);
            ull sa0 = pack2(xa0, xa0), sa1 = pack2(xa1, xa1);
            ull sb0 = pack2(xb0, xb0), sb1 = pack2(xb1, xb1);
            const ulonglong2* A0 = (const ulonglong2*)(sA2 + (2 * j2) * 32);
            const ulonglong2* A1 = (const ulonglong2*)(sA2 + (2 * j2 + 1) * 32);
            #pragma unroll
            for (int k2 = 0; k2 < 16; k2++) {
                ulonglong2 aa = A0[k2];
                fma2ip(acc2a[2 * k2 + 0], aa.x, sa0);
                fma2ip(acc2a[2 * k2 + 1], aa.y, sa0);
                fma2ip(acc2b[2 * k2 + 0], aa.x, sb0);
                fma2ip(acc2b[2 * k2 + 1], aa.y, sb0);
                ulonglong2 ab = A1[k2];
                fma2ip(acc2a[2 * k2 + 0], ab.x, sa1);
                fma2ip(acc2a[2 * k2 + 1], ab.y, sa1);
                fma2ip(acc2b[2 * k2 + 0], ab.x, sb1);
                fma2ip(acc2b[2 * k2 + 1], ab.y, sb1);
            }
        }

        upa += NU * R;
        ypa += NY * R;
        xpa += NX * R;
    }
}

#define SMEM_P3 (32768 + 16384 + 2048 + 2048 + 256)
#define SMEM_P0 ((4096 + 4096 + 8192) * 4)
#define SMEM_F  (32768 + 16384 + 8192 + 4096)

// ---------------------------------------------------------------------------
extern "C" void kernel_launch(void* const* d_in, const int* in_sizes, int n_in,
                              void* d_out, int out_size) {
    const float* u  = (const float*)d_in[0];
    const float* x0 = (const float*)d_in[1];
    const float* A  = (const float*)d_in[2];
    const float* B  = (const float*)d_in[3];
    const float* Cy = (const float*)d_in[4];
    const float* D  = (const float*)d_in[5];
    float* outY = (float*)d_out;
    float* outX = (float*)d_out + (size_t)N_STEPS * NY * R;

    cudaFuncSetAttribute(k_phase3, cudaFuncAttributeMaxDynamicSharedMemorySize, SMEM_P3);
    cudaFuncSetAttribute(k_precompute, cudaFuncAttributeMaxDynamicSharedMemorySize, SMEM_P0);
    cudaFuncSetAttribute(k_p12a, cudaFuncAttributeMaxDynamicSharedMemorySize, SMEM_F);

    k_precompute<<<1, 512, SMEM_P0>>>(A, B);
    k_p12a<<<dim3(NSUP, R / 16), 256, SMEM_F>>>(u);
    k_phase2b<<<R / 2, 128>>>(x0);
    k_phase3<<<dim3(C_CHUNKS, 2), 64, SMEM_P3>>>(u, A, B, Cy, D, outY, outX);
}

// round 17
// speedup vs baseline: 1.3200x; 1.2861x over previous
#include <cuda_runtime.h>
#include <cstddef>

#define N_STEPS 4096
#define NU 8
#define R 256
#define NX 64
#define NY 8
#define L 16
#define C_CHUNKS (N_STEPS / L)   // 256
#define QTOT (NU * L)            // 128

typedef unsigned long long ull;

// Scratch (device globals). g_buf layout: [c][r][i] (i contiguous).
__device__ float g_KcatT[QTOT * NX];
__device__ float g_AL[NX * NX];
__device__ float g_buf[(size_t)C_CHUNKS * NX * R];

// ---------------- packed f32x2 helpers ----------------
__device__ __forceinline__ ull pack2(float lo, float hi) {
    ull v; asm("mov.b64 %0,{%1,%2};" : "=l"(v) : "f"(lo), "f"(hi)); return v;
}
__device__ __forceinline__ void unpack2(ull v, float& lo, float& hi) {
    asm("mov.b64 {%0,%1},%2;" : "=f"(lo), "=f"(hi) : "l"(v));
}
__device__ __forceinline__ void fma2ip(ull& d, ull a, ull b) {
    asm("fma.rn.f32x2 %0,%1,%2,%0;" : "+l"(d) : "l"(a), "l"(b));
}

// ---------------------------------------------------------------------------
// Kernel 0 (R9/R14): K[s]=A^s B by doubling + A^16, all in smem. 512 threads.
// ---------------------------------------------------------------------------
extern __shared__ float psm[];
__global__ void k_precompute(const float* __restrict__ A, const float* __restrict__ B) {
    float* sP = psm;
    float* sQ = psm + 4096;
    float* sW = psm + 8192;
    const int t = threadIdx.x;
    const int i = t >> 3;
    const int g = t & 7;

    for (int idx = t; idx < NX * NX; idx += 512) sP[idx] = A[idx];
    for (int idx = t; idx < NX * NU; idx += 512)
        sW[(idx / NU) * QTOT + (idx % NU)] = B[idx];
    __syncthreads();

    float* p = sP;
    float* q = sQ;
    int w = NU;
    for (int m = 0; m < 4; m++) {
        const int cw = w >> 3;
        if (cw == 1) {
            float s0 = 0.f, s1 = 0.f, s2 = 0.f, s3 = 0.f;
            #pragma unroll 4
            for (int k = 0; k < NX; k += 4) {
                s0 += p[i * NX + k + 0] * sW[(k + 0) * QTOT + g];
                s1 += p[i * NX + k + 1] * sW[(k + 1) * QTOT + g];
                s2 += p[i * NX + k + 2] * sW[(k + 2) * QTOT + g];
                s3 += p[i * NX + k + 3] * sW[(k + 3) * QTOT + g];
            }
            sW[i * QTOT + w + g] = (s0 + s1) + (s2 + s3);
        } else {
            const int jc0 = g * cw;
            const int nv = cw >> 1;
            ull acc[4] = {0ull, 0ull, 0ull, 0ull};
            for (int k = 0; k < NX; k++) {
                float a = p[i * NX + k];
                ull pk = pack2(a, a);
                const ull* wr = (const ull*)(sW + k * QTOT + jc0);
                #pragma unroll
                for (int v = 0; v < 4; v++)
                    if (v < nv) fma2ip(acc[v], pk, wr[v]);
            }
            ull* out = (ull*)(sW + i * QTOT + w + jc0);
            #pragma unroll
            for (int v = 0; v < 4; v++)
                if (v < nv) out[v] = acc[v];
        }
        {
            const int jb = g * 8;
            ull acc[4] = {0ull, 0ull, 0ull, 0ull};
            for (int k = 0; k < NX; k++) {
                float a = p[i * NX + k];
                ull pk = pack2(a, a);
                const ulonglong2* pr = (const ulonglong2*)(p + k * NX + jb);
                ulonglong2 w0 = pr[0], w1 = pr[1];
                fma2ip(acc[0], pk, w0.x);
                fma2ip(acc[1], pk, w0.y);
                fma2ip(acc[2], pk, w1.x);
                fma2ip(acc[3], pk, w1.y);
            }
            ull* out = (ull*)(q + i * NX + jb);
            out[0] = acc[0]; out[1] = acc[1]; out[2] = acc[2]; out[3] = acc[3];
        }
        __syncthreads();
        float* tmp = p; p = q; q = tmp;
        w <<= 1;
    }
    for (int idx = t; idx < NX * NX; idx += 512) g_AL[idx] = p[idx];
    for (int idx = t; idx < NX * QTOT; idx += 512) {
        int ii = idx >> 7, col = idx & 127;
        int s = col >> 3, j = col & 7;
        g_KcatT[(((L - 1 - s) * NU + j) * NX) + ii] = sW[ii * QTOT + col];
    }
}

// ---------------------------------------------------------------------------
// Kernel 1: Pfin[c] = Kcat(64x128) @ Uc(128x256) -> g_buf[c][r][i].
// Per-thread: 8 consecutive packed ull stores at row (r0+r).
// ---------------------------------------------------------------------------
__global__ void k_phase1(const float* __restrict__ u) {
    __shared__ __align__(16) float sU[64 * 64];
    __shared__ __align__(16) float sKT[64 * 64];
    const int c = blockIdx.x;
    const int r0 = blockIdx.y * 64;
    const int t = threadIdx.x;
    const int r = t & 63;
    const int ig = t >> 6;

    ull acc2[8];
    #pragma unroll
    for (int m = 0; m < 8; m++) acc2[m] = 0ull;
    const float* Uc = u + (size_t)c * L * NU * R;

    for (int qb = 0; qb < QTOT / 64; qb++) {
        __syncthreads();
        #pragma unroll
        for (int m = 0; m < 16; m++) {
            int qq = m * 4 + ig;
            sU[qq * 64 + r] = Uc[(size_t)(qb * 64 + qq) * R + r0 + r];
        }
        for (int idx = t; idx < 4096; idx += 256)
            sKT[idx] = g_KcatT[qb * 64 * 64 + idx];
        __syncthreads();
        #pragma unroll 8
        for (int qq = 0; qq < 64; qq++) {
            float uval = sU[qq * 64 + r];
            ull uv = pack2(uval, uval);
            const ulonglong2* k2p = (const ulonglong2*)(sKT + qq * 64 + ig * 16);
            #pragma unroll
            for (int m2 = 0; m2 < 4; m2++) {
                ulonglong2 kk = k2p[m2];
                fma2ip(acc2[2 * m2 + 0], kk.x, uv);
                fma2ip(acc2[2 * m2 + 1], kk.y, uv);
            }
        }
    }
    // transposed store: g_buf[(c*R + row)*NX + i], 8 consecutive ull per thread
    {
        ull* grow = (ull*)(g_buf + ((size_t)c * R + r0 + r) * NX) + ig * 8;
        #pragma unroll
        for (int m = 0; m < 8; m++) grow[m] = acc2[m];
    }
}

// ---------------------------------------------------------------------------
// Kernel 2 (R14 structure, transposed accesses): boundary scan, unrolled x4,
// static prefetch regs + static ping-pong. 128 CTAs x 128 threads.
// ---------------------------------------------------------------------------
__global__ void k_phase2(const float* __restrict__ x0) {
    __shared__ __align__(16) float sxf[2][2][NX];  // [buf][r][i]
    const int t = threadIdx.x;  // 128
    const int r = t & 1;
    const int i = t >> 1;
    const int rg = blockIdx.x * 2 + r;

    ull a2[32];
    const ull* arow = (const ull*)(g_AL + i * NX);
    #pragma unroll
    for (int j2 = 0; j2 < 32; j2++) a2[j2] = arow[j2];

    float xi = x0[i * R + rg];
    sxf[0][r][i] = xi;
    __syncthreads();

    const size_t stride = (size_t)R * NX;          // per-chunk stride (floats)
    float* gb = g_buf + (size_t)rg * NX + i;       // [c][rg][i]

    float pf0 = gb[0 * stride];
    float pf1 = gb[1 * stride];
    float pf2 = gb[2 * stride];
    float pf3 = gb[3 * stride];

#define P2_STEP(CC, PF, RB, WB)                                               \
    {                                                                         \
        gb[(size_t)(CC) * stride] = xi;   /* Xstart[CC] */                    \
        float pfnew = ((CC) + 4 < C_CHUNKS) ? gb[(size_t)((CC) + 4) * stride] \
                                            : 0.f;                            \
        const ull* xsrc = (const ull*)&sxf[RB][r][0];                         \
        ull A0 = 0ull, A1 = 0ull, A2 = 0ull, A3 = 0ull;                       \
        _Pragma("unroll")                                                     \
        for (int j2 = 0; j2 < 32; j2 += 4) {                                  \
            fma2ip(A0, a2[j2 + 0], xsrc[j2 + 0]);                             \
            fma2ip(A1, a2[j2 + 1], xsrc[j2 + 1]);                             \
            fma2ip(A2, a2[j2 + 2], xsrc[j2 + 2]);                             \
            fma2ip(A3, a2[j2 + 3], xsrc[j2 + 3]);                             \
        }                                                                     \
        float s0, s1, s2, s3, s4, s5, s6, s7;                                 \
        unpack2(A0, s0, s1); unpack2(A1, s2, s3);                             \
        unpack2(A2, s4, s5); unpack2(A3, s6, s7);                             \
        xi = (((s0 + s1) + (s2 + s3)) + ((s4 + s5) + (s6 + s7))) + (PF);      \
        (PF) = pfnew;                                                         \
        sxf[WB][r][i] = xi;                                                   \
        __syncthreads();                                                      \
    }

    #pragma unroll 1
    for (int c = 0; c < C_CHUNKS; c += 4) {
        P2_STEP(c + 0, pf0, 0, 1);
        P2_STEP(c + 1, pf1, 1, 0);
        P2_STEP(c + 2, pf2, 0, 1);
        P2_STEP(c + 3, pf3, 1, 0);
    }
#undef P2_STEP
}

// ---------------------------------------------------------------------------
// Kernel 3 (R14, init reads transposed Xstart): TWO columns per thread,
// packed f32x2 in-place, x_k in smem scratch. 64 thr, grid (C_CHUNKS, 2).
// ---------------------------------------------------------------------------
extern __shared__ __align__(16) char dsmem[];

__global__ void __launch_bounds__(64) k_phase3(
    const float* __restrict__ u, const float* __restrict__ A,
    const float* __restrict__ B, const float* __restrict__ Cy,
    const float* __restrict__ D,
    float* __restrict__ outY, float* __restrict__ outX)
{
    ull*   xs  = (ull*)dsmem;                          // [32][128] packed x pairs
    ull*   sA2 = (ull*)(dsmem + 32768);                // [j][i2] 64x32
    ull*   sB2 = (ull*)(dsmem + 32768 + 16384);        // [j][i2] 8x32
    ull*   sC2 = (ull*)(dsmem + 32768 + 16384 + 2048); // [o][j2] 8x32
    float* sD  = (float*)(dsmem + 32768 + 16384 + 4096);

    const int tid = threadIdx.x;                       // 64
    const int c = blockIdx.x;
    const int rA = blockIdx.y * 128 + tid;             // column a (col b = rA+64)

    for (int idx = tid; idx < 64 * 32; idx += 64) {
        int j = idx >> 5, i2 = idx & 31;
        sA2[idx] = pack2(A[(2 * i2) * NX + j], A[(2 * i2 + 1) * NX + j]);
    }
    for (int idx = tid; idx < NU * 32; idx += 64) {
        int j = idx >> 5, i2 = idx & 31;
        sB2[idx] = pack2(B[(2 * i2) * NU + j], B[(2 * i2 + 1) * NU + j]);
    }
    for (int idx = tid; idx < NY * 32; idx += 64) {
        int o = idx >> 5, j2 = idx & 31;
        sC2[idx] = pack2(Cy[o * NX + 2 * j2], Cy[o * NX + 2 * j2 + 1]);
    }
    if (tid < NY * NU) sD[tid] = D[tid];

    // start state from transposed g_buf: row rA (and rA+64) = 32 packed ull
    ull acc2a[32], acc2b[32];
    {
        const ull* xsa = (const ull*)(g_buf + ((size_t)c * R + rA) * NX);
        const ull* xsb = (const ull*)(g_buf + ((size_t)c * R + rA + 64) * NX);
        #pragma unroll
        for (int k = 0; k < 32; k++) {
            acc2a[k] = xsa[k];
            acc2b[k] = xsb[k];
        }
    }
    __syncthreads();

    const float* upa = u    + (size_t)c * L * NU * R + rA;
    float*       ypa = outY + (size_t)c * L * NY * R + rA;
    float*       xpa = outX + (size_t)c * L * NX * R + rA;

    #pragma unroll 1
    for (int step = 0; step < L; step++) {
        float ua[NU], ub[NU];
        #pragma unroll
        for (int j = 0; j < NU; j++) {
            ua[j] = upa[j * R];
            ub[j] = upa[j * R + 64];
        }

        #pragma unroll 2
        for (int o = 0; o < NY; o++) {
            ull ya = 0ull, yb = 0ull;
            const ulonglong2* c2 = (const ulonglong2*)(sC2 + o * 32);
            #pragma unroll
            for (int k2 = 0; k2 < 16; k2++) {
                ulonglong2 cc = c2[k2];
                fma2ip(ya, cc.x, acc2a[2 * k2 + 0]);
                fma2ip(ya, cc.y, acc2a[2 * k2 + 1]);
                fma2ip(yb, cc.x, acc2b[2 * k2 + 0]);
                fma2ip(yb, cc.y, acc2b[2 * k2 + 1]);
            }
            float la, ha; unpack2(ya, la, ha);
            float lb, hb; unpack2(yb, lb, hb);
            float dsa = 0.f, dsb = 0.f;
            #pragma unroll
            for (int j = 0; j < NU; j++) {
                float dv = sD[o * NU + j];
                dsa += dv * ua[j];
                dsb += dv * ub[j];
            }
            ypa[o * R]      = (la + ha) + dsa;
            ypa[o * R + 64] = (lb + hb) + dsb;
        }

        #pragma unroll
        for (int k = 0; k < 32; k++) {
            float la, ha; unpack2(acc2a[k], la, ha);
            float lb, hb; unpack2(acc2b[k], lb, hb);
            xpa[(2 * k) * R]          = la;
            xpa[(2 * k + 1) * R]      = ha;
            xpa[(2 * k) * R + 64]     = lb;
            xpa[(2 * k + 1) * R + 64] = hb;
            xs[k * 128 + tid]      = acc2a[k];
            xs[k * 128 + 64 + tid] = acc2b[k];
        }

        {
            #pragma unroll
            for (int k = 0; k < 32; k++) { acc2a[k] = 0ull; acc2b[k] = 0ull; }
            #pragma unroll 2
            for (int j = 0; j < NU; j++) {
                ull uaj = pack2(ua[j], ua[j]);
                ull ubj = pack2(ub[j], ub[j]);
                const ulonglong2* bj = (const ulonglong2*)(sB2 + j * 32);
                #pragma unroll
                for (int k2 = 0; k2 < 16; k2++) {
                    ulonglong2 bb = bj[k2];
                    fma2ip(acc2a[2 * k2 + 0], bb.x, uaj);
                    fma2ip(acc2a[2 * k2 + 1], bb.y, uaj);
                    fma2ip(acc2b[2 * k2 + 0], bb.x, ubj);
                    fma2ip(acc2b[2 * k2 + 1], bb.y, ubj);
                }
            }
        }

        #pragma unroll 2
        for (int j2 = 0; j2 < 32; j2++) {
            ull pa = xs[j2 * 128 + tid];
            ull pb = xs[j2 * 128 + 64 + tid];
            float xa0, xa1; unpack2(pa, xa0, xa1);
            float xb0, xb1; unpack2(pb, xb0, xb1);
            ull sa0 = pack2(xa0, xa0), sa1 = pack2(xa1, xa1);
            ull sb0 = pack2(xb0, xb0), sb1 = pack2(xb1, xb1);
            const ulonglong2* A0 = (const ulonglong2*)(sA2 + (2 * j2) * 32);
            const ulonglong2* A1 = (const ulonglong2*)(sA2 + (2 * j2 + 1) * 32);
            #pragma unroll
            for (int k2 = 0; k2 < 16; k2++) {
                ulonglong2 aa = A0[k2];
                fma2ip(acc2a[2 * k2 + 0], aa.x, sa0);
                fma2ip(acc2a[2 * k2 + 1], aa.y, sa0);
                fma2ip(acc2b[2 * k2 + 0], aa.x, sb0);
                fma2ip(acc2b[2 * k2 + 1], aa.y, sb0);
                ulonglong2 ab = A1[k2];
                fma2ip(acc2a[2 * k2 + 0], ab.x, sa1);
                fma2ip(acc2a[2 * k2 + 1], ab.y, sa1);
                fma2ip(acc2b[2 * k2 + 0], ab.x, sb1);
                fma2ip(acc2b[2 * k2 + 1], ab.y, sb1);
            }
        }

        upa += NU * R;
        ypa += NY * R;
        xpa += NX * R;
    }
}

#define SMEM_P3 (32768 + 16384 + 2048 + 2048 + 256)
#define SMEM_P0 ((4096 + 4096 + 8192) * 4)

// ---------------------------------------------------------------------------
extern "C" void kernel_launch(void* const* d_in, const int* in_sizes, int n_in,
                              void* d_out, int out_size) {
    const float* u  = (const float*)d_in[0];
    const float* x0 = (const float*)d_in[1];
    const float* A  = (const float*)d_in[2];
    const float* B  = (const float*)d_in[3];
    const float* Cy = (const float*)d_in[4];
    const float* D  = (const float*)d_in[5];
    float* outY = (float*)d_out;
    float* outX = (float*)d_out + (size_t)N_STEPS * NY * R;

    cudaFuncSetAttribute(k_phase3, cudaFuncAttributeMaxDynamicSharedMemorySize, SMEM_P3);
    cudaFuncSetAttribute(k_precompute, cudaFuncAttributeMaxDynamicSharedMemorySize, SMEM_P0);

    k_precompute<<<1, 512, SMEM_P0>>>(A, B);
    k_phase1<<<dim3(C_CHUNKS, R / 64), 256>>>(u);
    k_phase2<<<R / 2, 128>>>(x0);
    k_phase3<<<dim3(C_CHUNKS, 2), 64, SMEM_P3>>>(u, A, B, Cy, D, outY, outX);
}